// round 11
// baseline (speedup 1.0000x reference)
#include <cuda_runtime.h>
#include <cstdint>

// Depth-to-space r=4, x-major channel ordering:
//   out[b, c, y, x] = in[b, c*16 + 4*(x%4) + (y%4), y/4, x/4]
// in : (16, 4096, 32, 32) fp32  -> 256 MB
// out: (16, 256, 128, 128) fp32 -> 256 MB
//
// Champion memory pattern (reproduced 3x: ~78.3us kernel, 78.6% DRAM):
//  - 256-bit v8.f32 loads/stores, every access a full 32B sector
//  - per thread: 4 loads (one per xr channel) + 4 stores writing 128B dense
//  - one 512-thread CTA per (b,c): 64KB dense read span + 64KB dense write
// New (final probe): bit-reverse the low 8 bits of the block index so the
// concurrently-resident wave of CTAs is spread across the full 256MB span
// instead of sweeping two lockstep linear ramps (read+write) through the
// DRAM row space. Per-thread instruction stream is unchanged.

__global__ void __launch_bounds__(512) scale_transfer_v8s_kernel(
    const float* __restrict__ in, float* __restrict__ out)
{
    // swizzle: bit-reverse low 8 bits of blockIdx.x (grid = 4096 = 2^12)
    unsigned raw = blockIdx.x;
    unsigned lo = raw & 255u;
    lo = __brev(lo) >> 24;                    // reverse within 8 bits
    const unsigned blk = (raw & ~255u) | lo;  // b*256 + c, swizzled order

    const unsigned t  = threadIdx.x;          // 0..511
    const unsigned xq = t & 3;                // 8-float group in 32-float row
    const unsigned y  = t >> 2;               // 0..127

    const unsigned yr = y & 3;
    const unsigned yb = y >> 2;

    // input: channel base = blk*16 (+ 4*xr + yr); channel = 1024 floats
    const float* p =
        in + (((size_t)blk * 16u + yr) * 32u + yb) * 32u + xq * 8u;

    float r[4][8];
#pragma unroll
    for (int xr = 0; xr < 4; xr++) {
        const float* q = p + xr * 4096;
        asm volatile(
            "ld.global.nc.v8.f32 {%0,%1,%2,%3,%4,%5,%6,%7}, [%8];"
            : "=f"(r[xr][0]), "=f"(r[xr][1]), "=f"(r[xr][2]), "=f"(r[xr][3]),
              "=f"(r[xr][4]), "=f"(r[xr][5]), "=f"(r[xr][6]), "=f"(r[xr][7])
            : "l"(q));
    }

    // output: 32 consecutive floats (x = xq*32 .. xq*32+31) of row (blk, y)
    float* o = out + (size_t)blk * 16384u + y * 128u + xq * 32u;

#pragma unroll
    for (int j = 0; j < 4; j++) {
        int i0 = 2 * j, i1 = 2 * j + 1;
        asm volatile(
            "st.global.v8.f32 [%0], {%1,%2,%3,%4,%5,%6,%7,%8};"
            :
            : "l"(o + j * 8),
              "f"(r[0][i0]), "f"(r[1][i0]), "f"(r[2][i0]), "f"(r[3][i0]),
              "f"(r[0][i1]), "f"(r[1][i1]), "f"(r[2][i1]), "f"(r[3][i1])
            : "memory");
    }
}

extern "C" void kernel_launch(void* const* d_in, const int* in_sizes, int n_in,
                              void* d_out, int out_size)
{
    const float* in = (const float*)d_in[0];
    float* out = (float*)d_out;

    // 4096 (b,c) blocks, one 512-thread CTA each, swizzled launch order
    scale_transfer_v8s_kernel<<<4096, 512>>>(in, out);
}

// round 12
// speedup vs baseline: 1.0012x; 1.0012x over previous
#include <cuda_runtime.h>
#include <cstdint>

// Depth-to-space r=4, x-major channel ordering:
//   out[b, c, y, x] = in[b, c*16 + 4*(x%4) + (y%4), y/4, x/4]
// in : (16, 4096, 32, 32) fp32  -> 256 MB
// out: (16, 256, 128, 128) fp32 -> 256 MB
//
// FINAL champion (reproduced 4x at 78.1-78.6us kernel, 6.21-6.24 TB/s =
// ~78% of HBM spec — the measured mixed read/write DRAM ceiling):
//  - 256-bit v8.f32 loads/stores: every access is a full 32B sector
//  - per thread: 4 loads (one per xr source channel, 32B each) + 4 stores
//    writing 128B dense; a warp writes 8 consecutive output rows (4KB)
//  - no cache hints, natural register allocation / occupancy
// Bracketed and rejected (rounds 3-11): store-dense remap, 2x MLP,
// evict_first hints, reg-capped occupancy, smem staging, TMA staging,
// CTA geometry, launch-order swizzle — all neutral or negative. DRAM is
// the sole bottleneck (issue 4.3%, compute ~3%); nothing left to trade.

__global__ void __launch_bounds__(256) scale_transfer_v8_kernel(
    const float* __restrict__ in, float* __restrict__ out)
{
    unsigned tid = blockIdx.x * blockDim.x + threadIdx.x;
    // tid layout: b[4] c[8] y[7] xq8[2]  -> 16*256*128*4 = 2,097,152 threads
    unsigned xq = tid & 3;            // 8-float group within 32-float input row
    unsigned y  = (tid >> 2) & 127;
    unsigned c  = (tid >> 9) & 255;
    unsigned b  = tid >> 17;

    unsigned yr = y & 3;
    unsigned yb = y >> 2;

    // input float index; channel stride for xr is 4 channels = 4096 floats
    const float* p =
        in + (((b * 4096u + c * 16u + yr) * 32u + yb) * 32u + xq * 8u);

    float r[4][8];
#pragma unroll
    for (int xr = 0; xr < 4; xr++) {
        const float* q = p + xr * 4096;
        asm volatile(
            "ld.global.nc.v8.f32 {%0,%1,%2,%3,%4,%5,%6,%7}, [%8];"
            : "=f"(r[xr][0]), "=f"(r[xr][1]), "=f"(r[xr][2]), "=f"(r[xr][3]),
              "=f"(r[xr][4]), "=f"(r[xr][5]), "=f"(r[xr][6]), "=f"(r[xr][7])
            : "l"(q));
    }

    // output: 32 consecutive floats (x = xq*32 .. xq*32+31) of row (b,c,y)
    float* o = out + (((b * 256u + c) * 128u + y) * 128u + xq * 32u);

#pragma unroll
    for (int j = 0; j < 4; j++) {
        // out local x = 4*i + xr, group j covers i = 2j, 2j+1
        int i0 = 2 * j, i1 = 2 * j + 1;
        asm volatile(
            "st.global.v8.f32 [%0], {%1,%2,%3,%4,%5,%6,%7,%8};"
            :
            : "l"(o + j * 8),
              "f"(r[0][i0]), "f"(r[1][i0]), "f"(r[2][i0]), "f"(r[3][i0]),
              "f"(r[0][i1]), "f"(r[1][i1]), "f"(r[2][i1]), "f"(r[3][i1])
            : "memory");
    }
}

extern "C" void kernel_launch(void* const* d_in, const int* in_sizes, int n_in,
                              void* d_out, int out_size)
{
    const float* in = (const float*)d_in[0];
    float* out = (float*)d_out;

    const int total_threads = 16 * 256 * 128 * 4;  // 2,097,152
    const int block = 256;
    const int grid = total_threads / block;        // 8192

    scale_transfer_v8_kernel<<<grid, block>>>(in, out);
}